// round 17
// baseline (speedup 1.0000x reference)
#include <cuda_runtime.h>
#include <math.h>

#define BB 32
#define MM 20
#define NCC 80
#define RM 16
#define AA 8400
#define GRP 2100            // anchor quads per image
#define KTOP 10
#define NOC 144
#define MAXCAND 1280
#define MAXLIST (BB*MM*KTOP)

// ---------------- scratch (static device globals; no allocations) ----------------
__device__ float g_pbox[BB*AA*4];          // decoded boxes, feature units (xyxy)
__device__ float g_gt[BB*MM*6];            // x1,y1,x2,y2,label,mask_gt (image units)
__device__ int   g_cnt[BB*AA];             // # gts selecting this anchor
__device__ int   g_minm[BB*AA];            // min m among selectors (conflict owner)
__device__ unsigned long long g_ovm[BB*AA];// packed (ov_bits<<32)|(MM-1-m) argmax
__device__ int   g_selAnchor[MAXLIST];     // selected anchors per gt (-1 unused)
__device__ float g_selAl[MAXLIST];
__device__ float g_selOv[MAXLIST];
__device__ float g_posA[BB*MM];            // max align over resolved positives per gt
__device__ float g_posO[BB*MM];
__device__ int   g_nA;                     // assignment list length
__device__ int   g_La[MAXLIST];            // b*AA + a
__device__ int   g_Lbm[MAXLIST];           // b*MM + m
__device__ float g_LAl[MAXLIST];
__device__ unsigned int g_done;            // loss-block completion counter
__device__ double g_acc[8];                // 0:S0 1:tss 2:x*t 3:box 4:dfl

__constant__ int   c_W[3]   = {80,40,20};
__constant__ int   c_OFF[3] = {0,6400,8000};
__constant__ int   c_HW[3]  = {6400,1600,400};
__constant__ float c_S[3]   = {8.f,16.f,32.f};

// ---------------- helpers ----------------
__device__ __forceinline__ void anch(int a, int &lvl, int &hw, int &local,
                                     float &stride, float &ax, float &ay) {
    if (a < 6400)      { lvl=0; hw=6400; local=a;      stride=8.f;  int y=local/80, x=local-y*80; ax=x+0.5f; ay=y+0.5f; }
    else if (a < 8000) { lvl=1; hw=1600; local=a-6400; stride=16.f; int y=local/40, x=local-y*40; ax=x+0.5f; ay=y+0.5f; }
    else               { lvl=2; hw=400;  local=a-8000; stride=32.f; int y=local/20, x=local-y*20; ax=x+0.5f; ay=y+0.5f; }
}

__device__ __forceinline__ float ciou_f(float b1x1,float b1y1,float b1x2,float b1y2,
                                        float b2x1,float b2y1,float b2x2,float b2y2){
    const float eps=1e-7f;
    float w1=b1x2-b1x1, h1=b1y2-b1y1+eps;
    float w2=b2x2-b2x1, h2=b2y2-b2y1+eps;
    float iw=fminf(b1x2,b2x2)-fmaxf(b1x1,b2x1); iw=fmaxf(iw,0.f);
    float ih=fminf(b1y2,b2y2)-fmaxf(b1y1,b2y1); ih=fmaxf(ih,0.f);
    float inter=iw*ih;
    float uni=w1*h1+w2*h2-inter+eps;
    float iou=inter/uni;
    float cw=fmaxf(b1x2,b2x2)-fminf(b1x1,b2x1);
    float ch=fmaxf(b1y2,b2y2)-fminf(b1y1,b2y1);
    float c2=cw*cw+ch*ch+eps;
    float dx=b2x1+b2x2-b1x1-b1x2, dy=b2y1+b2y2-b1y1-b1y2;
    float rho2=(dx*dx+dy*dy)*0.25f;
    float dv=atanf(w2/h2)-atanf(w1/h1);
    float v=0.4052847345693511f*dv*dv;     // 4/pi^2
    float al=v/(v-iou+1.0f+eps);
    return iou-(rho2/c2+v*al);
}

// b1 = gt (atan(w1/h1) precomputed as atg), b2 = pred. Bit-identical math to ciou_f.
__device__ __forceinline__ float ciou_pre(float b1x1,float b1y1,float b1x2,float b1y2,
                                          float b2x1,float b2y1,float b2x2,float b2y2,
                                          float atg){
    const float eps=1e-7f;
    float w1=b1x2-b1x1, h1=b1y2-b1y1+eps;
    float w2=b2x2-b2x1, h2=b2y2-b2y1+eps;
    float iw=fminf(b1x2,b2x2)-fmaxf(b1x1,b2x1); iw=fmaxf(iw,0.f);
    float ih=fminf(b1y2,b2y2)-fmaxf(b1y1,b2y1); ih=fmaxf(ih,0.f);
    float inter=iw*ih;
    float uni=w1*h1+w2*h2-inter+eps;
    float iou=inter/uni;
    float cw=fmaxf(b1x2,b2x2)-fminf(b1x1,b2x1);
    float ch=fmaxf(b1y2,b2y2)-fminf(b1y1,b2y1);
    float c2=cw*cw+ch*ch+eps;
    float dx=b2x1+b2x2-b1x1-b1x2, dy=b2y1+b2y2-b1y1-b1y2;
    float rho2=(dx*dx+dy*dy)*0.25f;
    float dv=atanf(w2/h2)-atg;
    float v=0.4052847345693511f*dv*dv;     // 4/pi^2
    float al=v/(v-iou+1.0f+eps);
    return iou-(rho2/c2+v*al);
}

__device__ __forceinline__ float softplus_neg_abs(float x){
    return fmaxf(x,0.f) + __logf(1.f + __expf(-fabsf(x)));
}

// ---------------- kernels ----------------
__global__ void k_init(const float* __restrict__ tg){
    int t=blockIdx.x*blockDim.x+threadIdx.x;
    if (t<BB*AA){ g_cnt[t]=0; g_minm[t]=0x7fffffff; g_ovm[t]=0ULL; }
    if (t<BB*MM){
        g_posA[t]=0.f; g_posO[t]=0.f;
        const float* r=tg+t*6;
        float cx=r[2]*640.f, cy=r[3]*640.f, w=r[4]*640.f, h=r[5]*640.f;
        float x1=cx-w*0.5f, y1=cy-h*0.5f, x2=cx+w*0.5f, y2=cy+h*0.5f;
        float* o=g_gt+t*6;
        o[0]=x1;o[1]=y1;o[2]=x2;o[3]=y2;o[4]=r[1];
        o[5]=(x1+y1+x2+y2>0.f)?1.f:0.f;
    }
    if (t<8) g_acc[t]=0.0;
    if (t==0){ g_nA=0; g_done=0u; }
}

// BCE target-independent term: pure linear grid-stride reduction over the
// contiguous cls slabs (channels 64..143 of each (b,level) block).
__global__ void __launch_bounds__(256) k_bce(const float* __restrict__ f0,
                        const float* __restrict__ f1,const float* __restrict__ f2){
    __shared__ float s_red[8];
    int gsz = gridDim.x*blockDim.x;
    int t = blockIdx.x*blockDim.x+threadIdx.x;
    float s0=0.f;
    #pragma unroll
    for (int l=0;l<3;l++){
        const float* f = l==0?f0:(l==1?f1:f2);
        int hw4 = c_HW[l]>>2;              // hw in float4s
        int slab = NCC*hw4;                // cls slab length per b, in float4s
        int tot  = BB*slab;
        for (int i=t;i<tot;i+=gsz){
            int b=i/slab, off=i-b*slab;
            float4 x = ((const float4*)f)[(size_t)b*(NOC*hw4) + 64*hw4 + off];
            s0 += softplus_neg_abs(x.x)+softplus_neg_abs(x.y)
                + softplus_neg_abs(x.z)+softplus_neg_abs(x.w);
        }
    }
    #pragma unroll
    for (int o=16;o;o>>=1) s0 += __shfl_down_sync(0xffffffffu, s0, o);
    int lane=threadIdx.x&31, wid=threadIdx.x>>5;
    if (lane==0) s_red[wid]=s0;
    __syncthreads();
    if (wid==0){
        s0=(lane<8)?s_red[lane]:0.f;
        #pragma unroll
        for (int o=4;o;o>>=1) s0 += __shfl_down_sync(0xffffffffu, s0, o);
        if (lane==0) atomicAdd(&g_acc[0], (double)s0);
    }
}

// DFL decode only: 4 threads per anchor-quad, one DFL side each (16 float4 loads)
__global__ void __launch_bounds__(256) k_dfl(const float* __restrict__ f0,
                         const float* __restrict__ f1,const float* __restrict__ f2){
    int t = blockIdx.x*blockDim.x+threadIdx.x;   // exactly BB*GRP*4 threads (1050 blocks)
    int qg = t>>2, side = t&3;
    int b=qg/GRP, q=qg-b*GRP;
    int lvl,hw,local,W;
    if (q<1600)      { lvl=0; hw=6400; local=q*4;         W=80; }
    else if (q<2000) { lvl=1; hw=1600; local=(q-1600)*4;  W=40; }
    else             { lvl=2; hw=400;  local=(q-2000)*4;  W=20; }
    const float* f = lvl==0?f0:(lvl==1?f1:f2);
    const float4* base = (const float4*)(f + (size_t)(b*NOC)*hw) + (local>>2);
    int cs = hw>>2;   // channel stride in float4s
    float4 den=make_float4(0.f,0.f,0.f,0.f);
    float4 num=make_float4(0.f,0.f,0.f,0.f);
    #pragma unroll
    for (int j=0;j<16;j++){
        float4 v = base[(side*16+j)*cs];
        float ex=__expf(v.x), ey=__expf(v.y), ez=__expf(v.z), ew=__expf(v.w);
        float fj=(float)j;
        den.x+=ex; den.y+=ey; den.z+=ez; den.w+=ew;
        num.x+=ex*fj; num.y+=ey*fj; num.z+=ez*fj; num.w+=ew*fj;
    }
    float dd[4]={num.x/den.x, num.y/den.y, num.z/den.z, num.w/den.w};
    int a0 = c_OFF[lvl]+local;
    int y = local/W, x0 = local-y*W;
    float ay = y+0.5f;
    bool isX = (side&1)==0;                  // sides 0,2 -> x1,x2 ; 1,3 -> y1,y2
    float sign = (side<2)? -1.f : 1.f;
    #pragma unroll
    for (int k=0;k<4;k++){
        float coord = isX ? ((float)(x0+k)+0.5f) : ay;
        g_pbox[(size_t)(b*AA+a0+k)*4 + side] = coord + sign*dd[k];
    }
}

// per (b,m): 256-thread enumeration (uniform trip count, gt-side atan hoisted)
// + warp-0 shuffle-only top-10
__global__ void __launch_bounds__(256) k_assign(const float* __restrict__ f0,
                        const float* __restrict__ f1,const float* __restrict__ f2){
    __shared__ unsigned long long s_key[MAXCAND];  // (al_bits<<32)|~idx
    __shared__ float s_ov[MAXCAND];
    __shared__ int s_n;

    int bm=blockIdx.x; int b=bm/MM; int m=bm-b*MM;
    int tid=threadIdx.x, lane=tid&31, wid=tid>>5;
    const float* g=g_gt+bm*6;
    float gx1=g[0],gy1=g[1],gx2=g[2],gy2=g[3];
    int label=(int)g[4];
    float mg=g[5];
    // gt-side atan, constant per block (same expression as inside ciou_f)
    float atg = atanf((gx2-gx1)/(gy2-gy1+1e-7f));
    if (tid==0) s_n=0;
    __syncthreads();

    if (mg>0.f){
        unsigned long long mtag = (unsigned long long)(unsigned)(MM-1-m);
        for (int l=0;l<3;l++){
            float s=c_S[l]; int W=c_W[l], OFF=c_OFF[l], hw=c_HW[l];
            float inv=1.f/s;
            int xlo=max(0,(int)floorf(gx1*inv-0.5f));
            int xhi=min(W-1,(int)ceilf (gx2*inv-0.5f));
            int ylo=max(0,(int)floorf(gy1*inv-0.5f));
            int yhi=min(W-1,(int)ceilf (gy2*inv-0.5f));
            int nx=xhi-xlo+1, ny=yhi-ylo+1;
            if (nx<=0||ny<=0) continue;
            int tot=nx*ny;
            const float* f = l==0?f0:(l==1?f1:f2);
            // UNIFORM trip count: every thread sees every ballot
            for (int i0=0;i0<tot;i0+=256){
                int i=i0+tid;
                bool put=false; float al=0.f, ov=0.f; int a=0;
                if (i<tot){
                    int yy=i/nx, y=ylo+yy, x=xlo+i-yy*nx;
                    float cx=(x+0.5f)*s, cy=(y+0.5f)*s;
                    float mn=fminf(fminf(cx-gx1,cy-gy1),fminf(gx2-cx,gy2-cy));
                    if (mn>1e-9f){
                        int local=y*W+x;
                        a=OFF+local;
                        float4 pb=((const float4*)g_pbox)[b*AA+a];
                        ov=fmaxf(ciou_pre(gx1,gy1,gx2,gy2,
                                          pb.x*s,pb.y*s,pb.z*s,pb.w*s, atg),0.f);
                        if (ov>0.f){
                            unsigned long long pk=((unsigned long long)__float_as_uint(ov)<<32)|mtag;
                            atomicMax(&g_ovm[b*AA+a], pk);
                            float xs=f[(size_t)(b*NOC+64+label)*hw+local];
                            float sig=1.f/(1.f+__expf(-xs));
                            float ov2=ov*ov;
                            al=sqrtf(sig)*ov2*ov2*ov2;
                            put=true;
                        }
                    }
                }
                unsigned msk=__ballot_sync(0xffffffffu, put);
                if (msk){
                    int leader=__ffs(msk)-1;
                    int base=0;
                    if (lane==leader) base=atomicAdd(&s_n,__popc(msk));
                    base=__shfl_sync(0xffffffffu,base,leader);
                    if (put){
                        int p=base+__popc(msk & ((1u<<lane)-1u));
                        s_key[p]=((unsigned long long)__float_as_uint(al)<<32)
                                |(unsigned)(~a);
                        s_ov[p]=ov;
                    }
                }
            }
        }
    }
    __syncthreads();

    // warp 0: shuffle-only top-10 over packed keys (val desc, idx asc; O(1) exclusion)
    if (wid==0){
        int n=s_n;
        int mySel=-1; float myA=0.f, myO=0.f;
        int cnt=0;
        for (int k=0;k<KTOP;k++){
            unsigned long long bk=0ULL; int bp=-1;
            for (int i=lane;i<n;i+=32){
                unsigned long long kk=s_key[i];
                if (kk>bk){ bk=kk; bp=i; }
            }
            #pragma unroll
            for (int o=16;o;o>>=1){
                unsigned long long ok=__shfl_down_sync(0xffffffffu,bk,o);
                int op=__shfl_down_sync(0xffffffffu,bp,o);
                if (ok>bk){ bk=ok; bp=op; }
            }
            bk=__shfl_sync(0xffffffffu,bk,0);
            bp=__shfl_sync(0xffffffffu,bp,0);
            float wv=__uint_as_float((unsigned)(bk>>32));
            if (wv<=0.f) break;            // uniform: bk broadcast from lane 0
            if (lane==k){ mySel=(int)(~(unsigned)bk); myA=wv; myO=s_ov[bp]; }
            if (lane==0) s_key[bp]=0ULL;
            __syncwarp();
            cnt=k+1;
        }
        if (lane<KTOP){
            int e=bm*KTOP+lane;
            if (lane<cnt){
                g_selAnchor[e]=mySel; g_selAl[e]=myA; g_selOv[e]=myO;
                atomicAdd(&g_cnt[b*AA+mySel],1);
                atomicMin(&g_minm[b*AA+mySel],m);
            } else {
                g_selAnchor[e]=-1;
            }
        }
    }
}

// resolve multi-gt anchors; warp-aggregated list append
__global__ void k_resolve(const float* __restrict__ f0,const float* __restrict__ f1,
                          const float* __restrict__ f2){
    int e=blockIdx.x*blockDim.x+threadIdx.x;
    int lane=threadIdx.x&31;
    bool emit=false;
    int key=0, bmOut=0; float outAl=0.f, outOv=0.f;
    if (e<MAXLIST){
        int bm=e/KTOP; int b=bm/MM; int m=bm-b*MM;
        int a=g_selAnchor[e];
        if (a>=0){
            key=b*AA+a;
            int cnt=g_cnt[key];
            if (cnt==1){
                emit=true; bmOut=bm; outAl=g_selAl[e]; outOv=g_selOv[e];
            } else if (g_minm[key]==m){   // one owner per conflicted anchor
                emit=true;
                unsigned long long pk=g_ovm[key];
                int outm = MM-1-(int)(unsigned)(pk & 0xffffffffULL);
                outOv = __uint_as_float((unsigned)(pk>>32));
                bmOut = b*MM+outm;
                int label=(int)g_gt[bmOut*6+4];
                int lvl,hw,local; float stride,ax,ay;
                anch(a,lvl,hw,local,stride,ax,ay);
                const float* f = lvl==0?f0:(lvl==1?f1:f2);
                float xs=f[(size_t)(b*NOC+64+label)*hw+local];
                float sig=1.f/(1.f+__expf(-xs));
                float ov2=outOv*outOv;
                outAl=sqrtf(sig)*ov2*ov2*ov2;
            }
        }
    }
    unsigned mask=__ballot_sync(0xffffffffu, emit);
    if (mask){
        int leader=__ffs(mask)-1;
        int baseIdx=0;
        if (lane==leader) baseIdx=atomicAdd(&g_nA,__popc(mask));
        baseIdx=__shfl_sync(0xffffffffu,baseIdx,leader);
        if (emit){
            int i=baseIdx+__popc(mask & ((1u<<lane)-1u));
            g_La[i]=key; g_Lbm[i]=bmOut; g_LAl[i]=outAl;
            atomicMax((int*)&g_posA[bmOut], __float_as_int(outAl));
            atomicMax((int*)&g_posO[bmOut], __float_as_int(outOv));
        }
    }
}

// per-assignment losses, 4 threads per assignment (one per DFL side) + fused finalize
__global__ void __launch_bounds__(256) k_loss(const float* __restrict__ f0,
                       const float* __restrict__ f1,const float* __restrict__ f2,
                       float* out, int out_size){
    int t=blockIdx.x*blockDim.x+threadIdx.x;
    int i=t>>2, side=t&3;
    int n=g_nA;
    double tss=0,xt=0,lb=0,ld=0;
    float dfl_s=0.f;
    bool act=(i<n);
    int key=0,b=0,a=0,bm=0,lvl=0,hw=0,local=0; float stride=8.f,ax=0.f,ay=0.f,norm=0.f;
    const float* cbase=nullptr; const float* g=nullptr;
    if (act){
        key=g_La[i]; b=key/AA; a=key-b*AA;
        bm=g_Lbm[i];
        norm=g_LAl[i]*g_posO[bm]/(g_posA[bm]+1e-9f);
        g=g_gt+bm*6;
        anch(a,lvl,hw,local,stride,ax,ay);
        const float* f = lvl==0?f0:(lvl==1?f1:f2);
        cbase=f+(size_t)(b*NOC)*hw+local;
        float inv=1.f/stride;
        float gv=g[side]*inv;
        float coord=(side&1)?ay:ax;
        float tval=(side<2)?(coord-gv):(gv-coord);
        tval=fminf(fmaxf(tval,0.f),14.99f);
        int tl=(int)tval;
        float wl=(float)(tl+1)-tval;
        float den=0.f, vl=0.f, vr=0.f;
        #pragma unroll
        for (int j=0;j<16;j++){
            float v=cbase[(size_t)(side*16+j)*hw];
            den+=__expf(v);
            if (j==tl)   vl=v;
            if (j==tl+1) vr=v;
        }
        float ls=__logf(den);
        dfl_s = -(vl-ls)*wl - (vr-ls)*(1.f-wl);
    }
    dfl_s += __shfl_xor_sync(0xffffffffu, dfl_s, 1);
    dfl_s += __shfl_xor_sync(0xffffffffu, dfl_s, 2);
    if (act && side==0){
        int label=(int)g[4];
        float x=cbase[(size_t)(64+label)*hw];
        tss=(double)norm;
        xt=(double)(x*norm);
        float inv=1.f/stride;
        float tx1=g[0]*inv, ty1=g[1]*inv, tx2=g[2]*inv, ty2=g[3]*inv;
        float4 pb=((const float4*)g_pbox)[key];
        float cio=ciou_f(pb.x,pb.y,pb.z,pb.w, tx1,ty1,tx2,ty2);
        lb=(double)((1.f-cio)*norm);
        ld=(double)(dfl_s*0.25f*norm);
    }
    for (int o=16;o;o>>=1){
        tss+=__shfl_down_sync(0xffffffffu,tss,o);
        xt +=__shfl_down_sync(0xffffffffu,xt ,o);
        lb +=__shfl_down_sync(0xffffffffu,lb ,o);
        ld +=__shfl_down_sync(0xffffffffu,ld ,o);
    }
    if ((threadIdx.x&31)==0){
        atomicAdd(&g_acc[1],tss);
        atomicAdd(&g_acc[2],xt);
        atomicAdd(&g_acc[3],lb);
        atomicAdd(&g_acc[4],ld);
    }
    __syncthreads();
    if (threadIdx.x==0){
        __threadfence();
        unsigned prev=atomicAdd(&g_done,1u);
        if (prev==gridDim.x-1u){
            volatile double* A=g_acc;
            double S0=A[0], tsum=A[1], xts=A[2], lbn=A[3], ldn=A[4];
            double T = tsum>1.0 ? tsum : 1.0;
            double lbox=lbn/T*7.5;
            double lcls=(S0-xts)/T*0.5;
            double ldfl=ldn/T*1.5;
            double tot=(lbox+lcls+ldfl)*32.0;
            for (int j=0;j<out_size;j++) out[j]=0.f;
            if (out_size>=4){ out[0]=(float)tot; out[1]=(float)lbox; out[2]=(float)lcls; out[3]=(float)ldfl; }
            else if (out_size==3){ out[0]=(float)lbox; out[1]=(float)lcls; out[2]=(float)ldfl; }
            else if (out_size>=1){ out[0]=(float)tot; }
        }
    }
}

extern "C" void kernel_launch(void* const* d_in, const int* in_sizes, int n_in,
                              void* d_out, int out_size){
    const float *f0=nullptr,*f1=nullptr,*f2=nullptr,*tg=nullptr;
    for (int i=0;i<n_in;i++){
        int s=in_sizes[i];
        if      (s==32*144*6400) f0=(const float*)d_in[i];
        else if (s==32*144*1600) f1=(const float*)d_in[i];
        else if (s==32*144*400)  f2=(const float*)d_in[i];
        else if (s==32*20*6)     tg=(const float*)d_in[i];
    }
    if(!f0) f0=(const float*)d_in[0];
    if(!f1) f1=(const float*)d_in[1];
    if(!f2) f2=(const float*)d_in[2];
    if(!tg) tg=(const float*)d_in[3];

    k_init<<<(BB*AA+255)/256,256>>>(tg);
    k_bce<<<1024,256>>>(f0,f1,f2);
    k_dfl<<<(BB*GRP*4)/256,256>>>(f0,f1,f2);
    k_assign<<<BB*MM,256>>>(f0,f1,f2);
    k_resolve<<<(MAXLIST+255)/256,256>>>(f0,f1,f2);
    k_loss<<<(MAXLIST*4+255)/256,256>>>(f0,f1,f2,(float*)d_out,out_size);
}